// round 2
// baseline (speedup 1.0000x reference)
#include <cuda_runtime.h>
#include <cuda_bf16.h>
#include <math.h>

// Problem constants
#define D_MODEL 1024
#define SEQ     2048
#define NHEADS  16
#define HEADDIM 64
#define MAXB    2

// ---------------------------------------------------------------------------
// Device scratch (static __device__ arrays — no allocation in kernel_launch)
// ---------------------------------------------------------------------------
__device__ float g_q[MAXB * SEQ * D_MODEL];
__device__ float g_k[MAXB * SEQ * D_MODEL];
__device__ float g_v[MAXB * SEQ * D_MODEL];
__device__ float g_ctx[MAXB * SEQ * D_MODEL];
// Fallback attn scratch only used if out_size doesn't include attn_weights
__device__ float g_attn[(size_t)MAXB * NHEADS * SEQ * SEQ];

// ---------------------------------------------------------------------------
// GEMM + bias: C[M,1024] = A[M,1024] @ W[1024,1024] + bias
// Tile: BM=64, BN=64, BK=16, 256 threads, 4x4 microtile per thread.
// ---------------------------------------------------------------------------
#define BM 64
#define BN 64
#define BK 16

__global__ void __launch_bounds__(256)
gemm_bias_kernel(const float* __restrict__ A, const float* __restrict__ W,
                 const float* __restrict__ bias, float* __restrict__ C)
{
    __shared__ float As[BK][BM + 1];   // transposed A tile: As[k][m]
    __shared__ float Bs[BK][BN];       // natural B tile (row stride 64 -> f4 ok)

    const int tid = threadIdx.x;
    const int tx = tid & 15;
    const int ty = tid >> 4;
    const int m0 = blockIdx.y * BM;
    const int n0 = blockIdx.x * BN;

    float acc[4][4] = {};

    for (int k0 = 0; k0 < D_MODEL; k0 += BK) {
        // Load A tile: 64 rows x 16 cols (scalar STS into transposed tile)
        {
            int r = tid >> 2;           // 0..63
            int c = (tid & 3) * 4;      // 0,4,8,12
            float4 v = *(const float4*)&A[(size_t)(m0 + r) * D_MODEL + k0 + c];
            As[c + 0][r] = v.x;
            As[c + 1][r] = v.y;
            As[c + 2][r] = v.z;
            As[c + 3][r] = v.w;
        }
        // Load B tile: 16 rows x 64 cols (row stride 64 floats: f4-aligned)
        {
            int r = tid >> 4;           // 0..15
            int c = (tid & 15) * 4;     // 0..60
            float4 v = *(const float4*)&W[(size_t)(k0 + r) * D_MODEL + n0 + c];
            *(float4*)&Bs[r][c] = v;
        }
        __syncthreads();

        #pragma unroll
        for (int kk = 0; kk < BK; kk++) {
            float a[4], b[4];
            #pragma unroll
            for (int i = 0; i < 4; i++) a[i] = As[kk][ty * 4 + i];
            #pragma unroll
            for (int j = 0; j < 4; j++) b[j] = Bs[kk][tx * 4 + j];
            #pragma unroll
            for (int i = 0; i < 4; i++)
                #pragma unroll
                for (int j = 0; j < 4; j++)
                    acc[i][j] += a[i] * b[j];
        }
        __syncthreads();
    }

    #pragma unroll
    for (int i = 0; i < 4; i++) {
        int m = m0 + ty * 4 + i;
        #pragma unroll
        for (int j = 0; j < 4; j++) {
            int n = n0 + tx * 4 + j;
            C[(size_t)m * D_MODEL + n] = acc[i][j] + bias[n];
        }
    }
}

// ---------------------------------------------------------------------------
// Attention scores: S[bh][m][n] = scale * dot(q[b,m,h,:], k[b,n,h,:]) over 64
// ---------------------------------------------------------------------------
__global__ void __launch_bounds__(256)
scores_kernel(const float* __restrict__ qb, const float* __restrict__ kb,
              const float* __restrict__ scale_ptr, float* __restrict__ attn)
{
    const int bh = blockIdx.z;
    const int b = bh >> 4;
    const int h = bh & 15;
    const int m0 = blockIdx.y * 64;
    const int n0 = blockIdx.x * 64;

    __shared__ float Qs[64][65];
    __shared__ float Ks[64][65];

    const int tid = threadIdx.x;
    const float* qbase = qb + (size_t)(b * SEQ + m0) * D_MODEL + h * HEADDIM;
    const float* kbase = kb + (size_t)(b * SEQ + n0) * D_MODEL + h * HEADDIM;

    #pragma unroll
    for (int i = 0; i < 4; i++) {
        int idx = tid + i * 256;          // 0..1023 float4 slots
        int r = idx >> 4;                 // 0..63
        int c = (idx & 15) * 4;           // 0..60
        float4 q4 = *(const float4*)&qbase[(size_t)r * D_MODEL + c];
        float4 k4 = *(const float4*)&kbase[(size_t)r * D_MODEL + c];
        Qs[r][c + 0] = q4.x; Qs[r][c + 1] = q4.y; Qs[r][c + 2] = q4.z; Qs[r][c + 3] = q4.w;
        Ks[r][c + 0] = k4.x; Ks[r][c + 1] = k4.y; Ks[r][c + 2] = k4.z; Ks[r][c + 3] = k4.w;
    }
    __syncthreads();

    const int tx = tid & 15;
    const int ty = tid >> 4;
    float acc[4][4] = {};

    #pragma unroll 16
    for (int kk = 0; kk < 64; kk++) {
        float a[4], bb[4];
        #pragma unroll
        for (int i = 0; i < 4; i++) a[i] = Qs[ty * 4 + i][kk];
        #pragma unroll
        for (int j = 0; j < 4; j++) bb[j] = Ks[tx * 4 + j][kk];
        #pragma unroll
        for (int i = 0; i < 4; i++)
            #pragma unroll
            for (int j = 0; j < 4; j++)
                acc[i][j] += a[i] * bb[j];
    }

    const float scale = scale_ptr[0];
    float* obase = attn + ((size_t)bh * SEQ + m0) * SEQ + n0;
    #pragma unroll
    for (int i = 0; i < 4; i++)
        #pragma unroll
        for (int j = 0; j < 4; j++)
            obase[(size_t)(ty * 4 + i) * SEQ + tx * 4 + j] = acc[i][j] * scale;
}

// ---------------------------------------------------------------------------
// Row softmax in place: one block (256 threads) per row of 2048.
// ---------------------------------------------------------------------------
__global__ void __launch_bounds__(256)
softmax_kernel(float* __restrict__ attn)
{
    const size_t row = blockIdx.x;
    float* p = attn + row * SEQ;
    const int tid = threadIdx.x;

    float local[8];
    float mx = -INFINITY;
    #pragma unroll
    for (int i = 0; i < 8; i++) {
        local[i] = p[tid + i * 256];
        mx = fmaxf(mx, local[i]);
    }

    __shared__ float red[256];
    red[tid] = mx;
    __syncthreads();
    #pragma unroll
    for (int s = 128; s > 0; s >>= 1) {
        if (tid < s) red[tid] = fmaxf(red[tid], red[tid + s]);
        __syncthreads();
    }
    mx = red[0];
    __syncthreads();

    float sum = 0.f;
    #pragma unroll
    for (int i = 0; i < 8; i++) {
        local[i] = __expf(local[i] - mx);
        sum += local[i];
    }
    red[tid] = sum;
    __syncthreads();
    #pragma unroll
    for (int s = 128; s > 0; s >>= 1) {
        if (tid < s) red[tid] += red[tid + s];
        __syncthreads();
    }
    const float inv = 1.0f / red[0];

    #pragma unroll
    for (int i = 0; i < 8; i++)
        p[tid + i * 256] = local[i] * inv;
}

// ---------------------------------------------------------------------------
// PV: ctx[b*SEQ+m][h*64+d] = sum_j P[bh][m][j] * v[b*SEQ+j][h*64+d]
// ---------------------------------------------------------------------------
__global__ void __launch_bounds__(256)
pv_kernel(const float* __restrict__ attn, const float* __restrict__ vb,
          float* __restrict__ ctx)
{
    const int bh = blockIdx.z;
    const int b = bh >> 4;
    const int h = bh & 15;
    const int m0 = blockIdx.x * 64;

    __shared__ float Ps[64][65];
    __shared__ float Vs[64][65];

    const int tid = threadIdx.x;
    const int tx = tid & 15;
    const int ty = tid >> 4;

    const float* pbase = attn + ((size_t)bh * SEQ + m0) * SEQ;
    const float* vbase = vb + (size_t)b * SEQ * D_MODEL + h * HEADDIM;

    float acc[4][4] = {};

    for (int k0 = 0; k0 < SEQ; k0 += 64) {
        #pragma unroll
        for (int i = 0; i < 4; i++) {
            int idx = tid + i * 256;
            int r = idx >> 4;
            int c = (idx & 15) * 4;
            float4 p4 = *(const float4*)&pbase[(size_t)r * SEQ + k0 + c];
            float4 v4 = *(const float4*)&vbase[(size_t)(k0 + r) * D_MODEL + c];
            Ps[r][c + 0] = p4.x; Ps[r][c + 1] = p4.y; Ps[r][c + 2] = p4.z; Ps[r][c + 3] = p4.w;
            Vs[r][c + 0] = v4.x; Vs[r][c + 1] = v4.y; Vs[r][c + 2] = v4.z; Vs[r][c + 3] = v4.w;
        }
        __syncthreads();

        #pragma unroll 16
        for (int kk = 0; kk < 64; kk++) {
            float a[4], bb[4];
            #pragma unroll
            for (int i = 0; i < 4; i++) a[i] = Ps[ty * 4 + i][kk];
            #pragma unroll
            for (int j = 0; j < 4; j++) bb[j] = Vs[kk][tx * 4 + j];
            #pragma unroll
            for (int i = 0; i < 4; i++)
                #pragma unroll
                for (int j = 0; j < 4; j++)
                    acc[i][j] += a[i] * bb[j];
        }
        __syncthreads();
    }

    #pragma unroll
    for (int i = 0; i < 4; i++) {
        int m = b * SEQ + m0 + ty * 4 + i;
        #pragma unroll
        for (int j = 0; j < 4; j++)
            ctx[(size_t)m * D_MODEL + h * HEADDIM + tx * 4 + j] = acc[i][j];
    }
}

// ---------------------------------------------------------------------------
// Launch
// ---------------------------------------------------------------------------
extern "C" void kernel_launch(void* const* d_in, const int* in_sizes, int n_in,
                              void* d_out, int out_size)
{
    const float* Q     = (const float*)d_in[0];
    const float* Wq    = (const float*)d_in[1];
    const float* bq    = (const float*)d_in[2];
    const float* Wk    = (const float*)d_in[3];
    const float* bk    = (const float*)d_in[4];
    const float* Wv    = (const float*)d_in[5];
    const float* bv    = (const float*)d_in[6];
    const float* Wo    = (const float*)d_in[7];
    const float* bo    = (const float*)d_in[8];
    const float* scale = (const float*)d_in[9];

    const int M = in_sizes[0] / D_MODEL;   // B * SEQ = 4096
    const int B = M / SEQ;                 // 2

    float* out = (float*)d_out;

    // Resolve scratch symbol addresses (not an allocation; capture-safe)
    float *qp, *kp, *vp, *cp, *ap;
    cudaGetSymbolAddress((void**)&qp, g_q);
    cudaGetSymbolAddress((void**)&kp, g_k);
    cudaGetSymbolAddress((void**)&vp, g_v);
    cudaGetSymbolAddress((void**)&cp, g_ctx);
    cudaGetSymbolAddress((void**)&ap, g_attn);

    // attn_weights target: second output region if present, else scratch
    const size_t out_elems  = (size_t)M * D_MODEL;
    float* attn = ((size_t)out_size > out_elems) ? (out + out_elems) : ap;

    dim3 gproj(D_MODEL / BN, M / BM);   // (16, 64)

    gemm_bias_kernel<<<gproj, 256>>>(Q, Wq, bq, qp);
    gemm_bias_kernel<<<gproj, 256>>>(Q, Wk, bk, kp);
    gemm_bias_kernel<<<gproj, 256>>>(Q, Wv, bv, vp);

    dim3 gsc(SEQ / 64, SEQ / 64, B * NHEADS);   // (32, 32, 32)
    scores_kernel<<<gsc, 256>>>(qp, kp, scale, attn);

    softmax_kernel<<<B * NHEADS * SEQ, 256>>>(attn);

    dim3 gpv(SEQ / 64, 1, B * NHEADS);          // (32, 1, 32)
    pv_kernel<<<gpv, 256>>>(attn, vp, cp);

    gemm_bias_kernel<<<gproj, 256>>>(cp, Wo, bo, out);
}

// round 3
// speedup vs baseline: 2.3897x; 2.3897x over previous
#include <cuda_runtime.h>
#include <cuda_bf16.h>
#include <math.h>
#include <stdint.h>

// Problem constants
#define D_MODEL 1024
#define SEQ     2048
#define NHEADS  16
#define HEADDIM 64
#define MAXB    2

// ---------------------------------------------------------------------------
// Device scratch
// ---------------------------------------------------------------------------
__device__ float g_q[MAXB * SEQ * D_MODEL];
__device__ float g_k[MAXB * SEQ * D_MODEL];
__device__ float g_v[MAXB * SEQ * D_MODEL];
__device__ float g_ctx[MAXB * SEQ * D_MODEL];
__device__ float g_attn[(size_t)MAXB * NHEADS * SEQ * SEQ];

// ---------------------------------------------------------------------------
// tf32 helpers
// ---------------------------------------------------------------------------
__device__ __forceinline__ uint32_t f2tf32(float x) {
    uint32_t r;
    asm("cvt.rna.tf32.f32 %0, %1;" : "=r"(r) : "f"(x));
    return r;
}

__device__ __forceinline__ void mma_tf32(float* c, const uint32_t* a, const uint32_t* b) {
    asm("mma.sync.aligned.m16n8k8.row.col.f32.tf32.tf32.f32 "
        "{%0,%1,%2,%3}, {%4,%5,%6,%7}, {%8,%9}, {%0,%1,%2,%3};"
        : "+f"(c[0]), "+f"(c[1]), "+f"(c[2]), "+f"(c[3])
        : "r"(a[0]), "r"(a[1]), "r"(a[2]), "r"(a[3]), "r"(b[0]), "r"(b[1]));
}

// ---------------------------------------------------------------------------
// GEMM + bias (tf32 tensor cores): C[M,1024] = A[M,1024] @ W[1024,1024] + b
// Block tile 128x128, BK=32, 256 threads (8 warps as 4x2 of 32x64 warp tiles)
// ---------------------------------------------------------------------------
__global__ void __launch_bounds__(256)
gemm_bias_tc(const float* __restrict__ A, const float* __restrict__ W,
             const float* __restrict__ bias, float* __restrict__ C)
{
    __shared__ uint32_t As[128][36];   // [m][k], pad->bank-clean frag reads
    __shared__ uint32_t Bs[32][132];   // [k][n]

    const int tid  = threadIdx.x;
    const int warp = tid >> 5;
    const int lane = tid & 31;
    const int g    = lane >> 2;        // 0..7
    const int kq   = lane & 3;         // 0..3
    const int wm   = warp >> 1;        // 0..3
    const int wn   = warp & 1;         // 0..1

    const int m0 = blockIdx.y * 128;
    const int n0 = blockIdx.x * 128;

    float acc[2][8][4] = {};

    for (int k0 = 0; k0 < D_MODEL; k0 += 32) {
        // A tile: 128x32 (1024 f4 slots)
        #pragma unroll
        for (int i = 0; i < 4; i++) {
            int idx = tid + i * 256;
            int r = idx >> 3, c4 = (idx & 7) * 4;
            float4 v = *(const float4*)&A[(size_t)(m0 + r) * D_MODEL + k0 + c4];
            As[r][c4 + 0] = f2tf32(v.x); As[r][c4 + 1] = f2tf32(v.y);
            As[r][c4 + 2] = f2tf32(v.z); As[r][c4 + 3] = f2tf32(v.w);
        }
        // B tile: 32x128
        #pragma unroll
        for (int i = 0; i < 4; i++) {
            int idx = tid + i * 256;
            int r = idx >> 5, c4 = (idx & 31) * 4;
            float4 v = *(const float4*)&W[(size_t)(k0 + r) * D_MODEL + n0 + c4];
            Bs[r][c4 + 0] = f2tf32(v.x); Bs[r][c4 + 1] = f2tf32(v.y);
            Bs[r][c4 + 2] = f2tf32(v.z); Bs[r][c4 + 3] = f2tf32(v.w);
        }
        __syncthreads();

        #pragma unroll
        for (int kk = 0; kk < 4; kk++) {
            const int k8 = kk * 8;
            uint32_t af[2][4];
            #pragma unroll
            for (int im = 0; im < 2; im++) {
                int rb = wm * 32 + im * 16;
                af[im][0] = As[rb + g][k8 + kq];
                af[im][1] = As[rb + g + 8][k8 + kq];
                af[im][2] = As[rb + g][k8 + kq + 4];
                af[im][3] = As[rb + g + 8][k8 + kq + 4];
            }
            uint32_t bf[8][2];
            #pragma unroll
            for (int jn = 0; jn < 8; jn++) {
                int cb = wn * 64 + jn * 8;
                bf[jn][0] = Bs[k8 + kq][cb + g];
                bf[jn][1] = Bs[k8 + kq + 4][cb + g];
            }
            #pragma unroll
            for (int im = 0; im < 2; im++)
                #pragma unroll
                for (int jn = 0; jn < 8; jn++)
                    mma_tf32(acc[im][jn], af[im], bf[jn]);
        }
        __syncthreads();
    }

    #pragma unroll
    for (int im = 0; im < 2; im++) {
        int mb = m0 + wm * 32 + im * 16;
        #pragma unroll
        for (int jn = 0; jn < 8; jn++) {
            int n = n0 + wn * 64 + jn * 8 + 2 * kq;
            float b0 = bias[n], b1 = bias[n + 1];
            float* p0 = &C[(size_t)(mb + g) * D_MODEL + n];
            float* p1 = &C[(size_t)(mb + g + 8) * D_MODEL + n];
            p0[0] = acc[im][jn][0] + b0; p0[1] = acc[im][jn][1] + b1;
            p1[0] = acc[im][jn][2] + b0; p1[1] = acc[im][jn][3] + b1;
        }
    }
}

// ---------------------------------------------------------------------------
// Attention scores (tf32): S[bh][m][n] = scale * q[m,:] . k[n,:]  (K=64)
// Block tile 128x128, BK=32, 2 K-steps.
// ---------------------------------------------------------------------------
__global__ void __launch_bounds__(256)
scores_tc(const float* __restrict__ qb, const float* __restrict__ kb,
          const float* __restrict__ scale_ptr, float* __restrict__ attn)
{
    __shared__ uint32_t As[128][36];    // q  [m][k]
    __shared__ uint32_t Ns[128][36];    // k  [n][k]  (B col-major == row of K)

    const int tid  = threadIdx.x;
    const int warp = tid >> 5;
    const int lane = tid & 31;
    const int g    = lane >> 2;
    const int kq   = lane & 3;
    const int wm   = warp >> 1;
    const int wn   = warp & 1;

    const int bh = blockIdx.z;
    const int b  = bh >> 4;
    const int h  = bh & 15;
    const int m0 = blockIdx.y * 128;
    const int n0 = blockIdx.x * 128;

    const float* qbase = qb + (size_t)(b * SEQ + m0) * D_MODEL + h * HEADDIM;
    const float* kbase = kb + (size_t)(b * SEQ + n0) * D_MODEL + h * HEADDIM;

    float acc[2][8][4] = {};

    for (int k0 = 0; k0 < HEADDIM; k0 += 32) {
        #pragma unroll
        for (int i = 0; i < 4; i++) {
            int idx = tid + i * 256;
            int r = idx >> 3, c4 = (idx & 7) * 4;
            float4 v = *(const float4*)&qbase[(size_t)r * D_MODEL + k0 + c4];
            As[r][c4 + 0] = f2tf32(v.x); As[r][c4 + 1] = f2tf32(v.y);
            As[r][c4 + 2] = f2tf32(v.z); As[r][c4 + 3] = f2tf32(v.w);
            float4 w = *(const float4*)&kbase[(size_t)r * D_MODEL + k0 + c4];
            Ns[r][c4 + 0] = f2tf32(w.x); Ns[r][c4 + 1] = f2tf32(w.y);
            Ns[r][c4 + 2] = f2tf32(w.z); Ns[r][c4 + 3] = f2tf32(w.w);
        }
        __syncthreads();

        #pragma unroll
        for (int kk = 0; kk < 4; kk++) {
            const int k8 = kk * 8;
            uint32_t af[2][4];
            #pragma unroll
            for (int im = 0; im < 2; im++) {
                int rb = wm * 32 + im * 16;
                af[im][0] = As[rb + g][k8 + kq];
                af[im][1] = As[rb + g + 8][k8 + kq];
                af[im][2] = As[rb + g][k8 + kq + 4];
                af[im][3] = As[rb + g + 8][k8 + kq + 4];
            }
            uint32_t bf[8][2];
            #pragma unroll
            for (int jn = 0; jn < 8; jn++) {
                int cb = wn * 64 + jn * 8;
                bf[jn][0] = Ns[cb + g][k8 + kq];
                bf[jn][1] = Ns[cb + g][k8 + kq + 4];
            }
            #pragma unroll
            for (int im = 0; im < 2; im++)
                #pragma unroll
                for (int jn = 0; jn < 8; jn++)
                    mma_tf32(acc[im][jn], af[im], bf[jn]);
        }
        __syncthreads();
    }

    const float scale = scale_ptr[0];
    float* obase = attn + ((size_t)bh * SEQ + m0) * SEQ + n0;
    #pragma unroll
    for (int im = 0; im < 2; im++) {
        int mb = wm * 32 + im * 16;
        #pragma unroll
        for (int jn = 0; jn < 8; jn++) {
            int n = wn * 64 + jn * 8 + 2 * kq;
            float* p0 = obase + (size_t)(mb + g) * SEQ + n;
            float* p1 = obase + (size_t)(mb + g + 8) * SEQ + n;
            p0[0] = acc[im][jn][0] * scale; p0[1] = acc[im][jn][1] * scale;
            p1[0] = acc[im][jn][2] * scale; p1[1] = acc[im][jn][3] * scale;
        }
    }
}

// ---------------------------------------------------------------------------
// Row softmax in place (unchanged)
// ---------------------------------------------------------------------------
__global__ void __launch_bounds__(256)
softmax_kernel(float* __restrict__ attn)
{
    const size_t row = blockIdx.x;
    float* p = attn + row * SEQ;
    const int tid = threadIdx.x;

    float local[8];
    float mx = -INFINITY;
    #pragma unroll
    for (int i = 0; i < 8; i++) {
        local[i] = p[tid + i * 256];
        mx = fmaxf(mx, local[i]);
    }

    __shared__ float red[256];
    red[tid] = mx;
    __syncthreads();
    #pragma unroll
    for (int s = 128; s > 0; s >>= 1) {
        if (tid < s) red[tid] = fmaxf(red[tid], red[tid + s]);
        __syncthreads();
    }
    mx = red[0];
    __syncthreads();

    float sum = 0.f;
    #pragma unroll
    for (int i = 0; i < 8; i++) {
        local[i] = __expf(local[i] - mx);
        sum += local[i];
    }
    red[tid] = sum;
    __syncthreads();
    #pragma unroll
    for (int s = 128; s > 0; s >>= 1) {
        if (tid < s) red[tid] += red[tid + s];
        __syncthreads();
    }
    const float inv = 1.0f / red[0];

    #pragma unroll
    for (int i = 0; i < 8; i++)
        p[tid + i * 256] = local[i] * inv;
}

// ---------------------------------------------------------------------------
// PV (tf32): ctx[m, h*64+d] = sum_j P[bh][m][j] * v[j, h*64+d]
// Block tile 128x64, BK=32, 64 K-steps. Warps 4x2 -> warp tile 32x32.
// ---------------------------------------------------------------------------
__global__ void __launch_bounds__(256)
pv_tc(const float* __restrict__ attn, const float* __restrict__ vb,
      float* __restrict__ ctx)
{
    __shared__ uint32_t As[128][36];   // P [m][k]
    __shared__ uint32_t Bs[32][68];    // V [k][n]

    const int tid  = threadIdx.x;
    const int warp = tid >> 5;
    const int lane = tid & 31;
    const int g    = lane >> 2;
    const int kq   = lane & 3;
    const int wm   = warp >> 1;        // 0..3
    const int wn   = warp & 1;         // 0..1

    const int bh = blockIdx.z;
    const int b  = bh >> 4;
    const int h  = bh & 15;
    const int m0 = blockIdx.x * 128;

    const float* pbase = attn + ((size_t)bh * SEQ + m0) * SEQ;
    const float* vbase = vb + (size_t)b * SEQ * D_MODEL + h * HEADDIM;

    float acc[2][4][4] = {};

    for (int k0 = 0; k0 < SEQ; k0 += 32) {
        // P tile 128x32
        #pragma unroll
        for (int i = 0; i < 4; i++) {
            int idx = tid + i * 256;
            int r = idx >> 3, c4 = (idx & 7) * 4;
            float4 v = *(const float4*)&pbase[(size_t)r * SEQ + k0 + c4];
            As[r][c4 + 0] = f2tf32(v.x); As[r][c4 + 1] = f2tf32(v.y);
            As[r][c4 + 2] = f2tf32(v.z); As[r][c4 + 3] = f2tf32(v.w);
        }
        // V tile 32x64 (512 f4 slots, 2 per thread)
        #pragma unroll
        for (int i = 0; i < 2; i++) {
            int idx = tid + i * 256;
            int r = idx >> 4, c4 = (idx & 15) * 4;
            float4 v = *(const float4*)&vbase[(size_t)(k0 + r) * D_MODEL + c4];
            Bs[r][c4 + 0] = f2tf32(v.x); Bs[r][c4 + 1] = f2tf32(v.y);
            Bs[r][c4 + 2] = f2tf32(v.z); Bs[r][c4 + 3] = f2tf32(v.w);
        }
        __syncthreads();

        #pragma unroll
        for (int kk = 0; kk < 4; kk++) {
            const int k8 = kk * 8;
            uint32_t af[2][4];
            #pragma unroll
            for (int im = 0; im < 2; im++) {
                int rb = wm * 32 + im * 16;
                af[im][0] = As[rb + g][k8 + kq];
                af[im][1] = As[rb + g + 8][k8 + kq];
                af[im][2] = As[rb + g][k8 + kq + 4];
                af[im][3] = As[rb + g + 8][k8 + kq + 4];
            }
            uint32_t bf[4][2];
            #pragma unroll
            for (int jn = 0; jn < 4; jn++) {
                int cb = wn * 32 + jn * 8;
                bf[jn][0] = Bs[k8 + kq][cb + g];
                bf[jn][1] = Bs[k8 + kq + 4][cb + g];
            }
            #pragma unroll
            for (int im = 0; im < 2; im++)
                #pragma unroll
                for (int jn = 0; jn < 4; jn++)
                    mma_tf32(acc[im][jn], af[im], bf[jn]);
        }
        __syncthreads();
    }

    #pragma unroll
    for (int im = 0; im < 2; im++) {
        int mb = b * SEQ + m0 + wm * 32 + im * 16;
        #pragma unroll
        for (int jn = 0; jn < 4; jn++) {
            int n = h * HEADDIM + wn * 32 + jn * 8 + 2 * kq;
            float* p0 = &ctx[(size_t)(mb + g) * D_MODEL + n];
            float* p1 = &ctx[(size_t)(mb + g + 8) * D_MODEL + n];
            p0[0] = acc[im][jn][0]; p0[1] = acc[im][jn][1];
            p1[0] = acc[im][jn][2]; p1[1] = acc[im][jn][3];
        }
    }
}

// ---------------------------------------------------------------------------
// Launch
// ---------------------------------------------------------------------------
extern "C" void kernel_launch(void* const* d_in, const int* in_sizes, int n_in,
                              void* d_out, int out_size)
{
    const float* Q     = (const float*)d_in[0];
    const float* Wq    = (const float*)d_in[1];
    const float* bq    = (const float*)d_in[2];
    const float* Wk    = (const float*)d_in[3];
    const float* bk    = (const float*)d_in[4];
    const float* Wv    = (const float*)d_in[5];
    const float* bv    = (const float*)d_in[6];
    const float* Wo    = (const float*)d_in[7];
    const float* bo    = (const float*)d_in[8];
    const float* scale = (const float*)d_in[9];

    const int M = in_sizes[0] / D_MODEL;   // B * SEQ
    const int B = M / SEQ;

    float* out = (float*)d_out;

    float *qp, *kp, *vp, *cp, *ap;
    cudaGetSymbolAddress((void**)&qp, g_q);
    cudaGetSymbolAddress((void**)&kp, g_k);
    cudaGetSymbolAddress((void**)&vp, g_v);
    cudaGetSymbolAddress((void**)&cp, g_ctx);
    cudaGetSymbolAddress((void**)&ap, g_attn);

    const size_t out_elems = (size_t)M * D_MODEL;
    float* attn = ((size_t)out_size > out_elems) ? (out + out_elems) : ap;

    dim3 gproj(D_MODEL / 128, M / 128);        // (8, 32)

    gemm_bias_tc<<<gproj, 256>>>(Q, Wq, bq, qp);
    gemm_bias_tc<<<gproj, 256>>>(Q, Wk, bk, kp);
    gemm_bias_tc<<<gproj, 256>>>(Q, Wv, bv, vp);

    dim3 gsc(SEQ / 128, SEQ / 128, B * NHEADS);  // (16, 16, 32)
    scores_tc<<<gsc, 256>>>(qp, kp, scale, attn);

    softmax_kernel<<<B * NHEADS * SEQ, 256>>>(attn);

    dim3 gpv(SEQ / 128, 1, B * NHEADS);          // (16, 1, 32)
    pv_tc<<<gpv, 256>>>(attn, vp, cp);

    gemm_bias_tc<<<gproj, 256>>>(cp, Wo, bo, out);
}

// round 4
// speedup vs baseline: 2.7112x; 1.1345x over previous
#include <cuda_runtime.h>
#include <cuda_bf16.h>
#include <math.h>
#include <stdint.h>

// Problem constants
#define D_MODEL 1024
#define SEQ     2048
#define NHEADS  16
#define HEADDIM 64
#define MAXB    2

// ---------------------------------------------------------------------------
// Device scratch
// ---------------------------------------------------------------------------
__device__ float g_q[MAXB * SEQ * D_MODEL];
__device__ float g_k[MAXB * SEQ * D_MODEL];
__device__ float g_v[MAXB * SEQ * D_MODEL];
__device__ float g_ctx[MAXB * SEQ * D_MODEL];
__device__ float g_attn[(size_t)MAXB * NHEADS * SEQ * SEQ];

// ---------------------------------------------------------------------------
// tf32 helpers
// ---------------------------------------------------------------------------
__device__ __forceinline__ uint32_t f2tf32(float x) {
    uint32_t r;
    asm("cvt.rna.tf32.f32 %0, %1;" : "=r"(r) : "f"(x));
    return r;
}

__device__ __forceinline__ void mma_tf32(float* c, const uint32_t* a, const uint32_t* b) {
    asm("mma.sync.aligned.m16n8k8.row.col.f32.tf32.tf32.f32 "
        "{%0,%1,%2,%3}, {%4,%5,%6,%7}, {%8,%9}, {%0,%1,%2,%3};"
        : "+f"(c[0]), "+f"(c[1]), "+f"(c[2]), "+f"(c[3])
        : "r"(a[0]), "r"(a[1]), "r"(a[2]), "r"(a[3]), "r"(b[0]), "r"(b[1]));
}

// Fragment-native SMEM layouts:
//   AF[mt][kb][lane] : uint4 = {A[g][kq], A[g+8][kq], A[g][kq+4], A[g+8][kq+4]}
//                      for m16-tile mt, k8-block kb, lane = g*4 + kq
//   BF[nt][kb][lane] : uint2 = {B[kq][n=g], B[kq+4][n=g]} (col-major operand)
// One LDS.128 per A-frag, one LDS.64 per B-frag, conflict-free.

struct GemmSmem {
    uint4 AF[8][4][33];   // 128 rows x 32 k
    uint2 BF[16][4][33];  // 32 k x 128 n
};

// ---------------------------------------------------------------------------
// Shared GEMM body: C[128,128 tile] = A[M,1024] @ W[1024,1024] + bias
// ---------------------------------------------------------------------------
__device__ __forceinline__ void gemm_body(
    GemmSmem& s, const float* __restrict__ A, const float* __restrict__ W,
    const float* __restrict__ bias, float* __restrict__ C, int m0, int n0)
{
    const int tid  = threadIdx.x;
    const int warp = tid >> 5;
    const int lane = tid & 31;
    const int g    = lane >> 2;
    const int kq   = lane & 3;
    const int wm   = warp >> 1;
    const int wn   = warp & 1;

    float acc[2][8][4] = {};

    for (int k0 = 0; k0 < D_MODEL; k0 += 32) {
        // A tile 128x32 -> AF
        #pragma unroll
        for (int i = 0; i < 2; i++) {
            int idx = tid + i * 256;
            int rp = idx >> 3;          // 0..63 (row-pair id)
            int c4 = (idx & 7) * 4;     // 0..28
            int mt = rp >> 3;
            int r8 = rp & 7;
            const float* a0 = &A[(size_t)(m0 + mt * 16 + r8) * D_MODEL + k0 + c4];
            float4 vlo = *(const float4*)a0;
            float4 vhi = *(const float4*)(a0 + 8 * D_MODEL);
            int kb  = c4 >> 3;
            int off = ((c4 >> 2) & 1) * 2;   // khi*2
            uint32_t* base = (uint32_t*)&s.AF[mt][kb][r8 * 4];
            *(uint2*)&base[0 * 4 + off] = make_uint2(f2tf32(vlo.x), f2tf32(vhi.x));
            *(uint2*)&base[1 * 4 + off] = make_uint2(f2tf32(vlo.y), f2tf32(vhi.y));
            *(uint2*)&base[2 * 4 + off] = make_uint2(f2tf32(vlo.z), f2tf32(vhi.z));
            *(uint2*)&base[3 * 4 + off] = make_uint2(f2tf32(vlo.w), f2tf32(vhi.w));
        }
        // B tile 32x128 -> BF
        #pragma unroll
        for (int i = 0; i < 2; i++) {
            int idx = tid + i * 256;
            int rp = idx >> 5;          // 0..15 (k row-pair id)
            int c4 = (idx & 31) * 4;    // 0..124
            int kb = rp >> 2;
            int rq = rp & 3;
            const float* b0 = &W[(size_t)(k0 + kb * 8 + rq) * D_MODEL + n0 + c4];
            float4 vlo = *(const float4*)b0;
            float4 vhi = *(const float4*)(b0 + 4 * D_MODEL);
            int nt = c4 >> 3;
            int gb = c4 & 7;            // 0 or 4
            s.BF[nt][kb][(gb + 0) * 4 + rq] = make_uint2(f2tf32(vlo.x), f2tf32(vhi.x));
            s.BF[nt][kb][(gb + 1) * 4 + rq] = make_uint2(f2tf32(vlo.y), f2tf32(vhi.y));
            s.BF[nt][kb][(gb + 2) * 4 + rq] = make_uint2(f2tf32(vlo.z), f2tf32(vhi.z));
            s.BF[nt][kb][(gb + 3) * 4 + rq] = make_uint2(f2tf32(vlo.w), f2tf32(vhi.w));
        }
        __syncthreads();

        #pragma unroll
        for (int kb = 0; kb < 4; kb++) {
            uint4 a[2];
            a[0] = s.AF[wm * 2 + 0][kb][lane];
            a[1] = s.AF[wm * 2 + 1][kb][lane];
            uint2 b[8];
            #pragma unroll
            for (int jn = 0; jn < 8; jn++) b[jn] = s.BF[wn * 8 + jn][kb][lane];
            #pragma unroll
            for (int im = 0; im < 2; im++)
                #pragma unroll
                for (int jn = 0; jn < 8; jn++)
                    mma_tf32(acc[im][jn], (const uint32_t*)&a[im], (const uint32_t*)&b[jn]);
        }
        __syncthreads();
    }

    #pragma unroll
    for (int im = 0; im < 2; im++) {
        int mb = m0 + wm * 32 + im * 16;
        #pragma unroll
        for (int jn = 0; jn < 8; jn++) {
            int n = n0 + wn * 64 + jn * 8 + 2 * kq;
            float b0 = bias[n], b1 = bias[n + 1];
            float* p0 = &C[(size_t)(mb + g) * D_MODEL + n];
            float* p1 = &C[(size_t)(mb + g + 8) * D_MODEL + n];
            p0[0] = acc[im][jn][0] + b0; p0[1] = acc[im][jn][1] + b1;
            p1[0] = acc[im][jn][2] + b0; p1[1] = acc[im][jn][3] + b1;
        }
    }
}

// Fused QKV projection: blockIdx.z selects {Wq,bq,q} / {Wk,bk,k} / {Wv,bv,v}
__global__ void __launch_bounds__(256)
qkv_proj_tc(const float* __restrict__ A,
            const float* __restrict__ Wq, const float* __restrict__ bq,
            const float* __restrict__ Wk, const float* __restrict__ bk,
            const float* __restrict__ Wv, const float* __restrict__ bv,
            float* __restrict__ oq, float* __restrict__ ok, float* __restrict__ ov)
{
    __shared__ GemmSmem s;
    const int z = blockIdx.z;
    const float* W    = (z == 0) ? Wq : (z == 1) ? Wk : Wv;
    const float* bias = (z == 0) ? bq : (z == 1) ? bk : bv;
    float*       C    = (z == 0) ? oq : (z == 1) ? ok : ov;
    gemm_body(s, A, W, bias, C, blockIdx.y * 128, blockIdx.x * 128);
}

__global__ void __launch_bounds__(256)
gemm_bias_tc(const float* __restrict__ A, const float* __restrict__ W,
             const float* __restrict__ bias, float* __restrict__ C)
{
    __shared__ GemmSmem s;
    gemm_body(s, A, W, bias, C, blockIdx.y * 128, blockIdx.x * 128);
}

// ---------------------------------------------------------------------------
// Attention scores: S = scale * Q K^T  (K-dim 64), tile 128x128
// ---------------------------------------------------------------------------
__global__ void __launch_bounds__(256)
scores_tc(const float* __restrict__ qb, const float* __restrict__ kb_,
          const float* __restrict__ scale_ptr, float* __restrict__ attn)
{
    __shared__ uint4 QF[8][4][33];
    __shared__ uint2 KF[16][4][33];

    const int tid  = threadIdx.x;
    const int warp = tid >> 5;
    const int lane = tid & 31;
    const int g    = lane >> 2;
    const int kq   = lane & 3;
    const int wm   = warp >> 1;
    const int wn   = warp & 1;

    const int bh = blockIdx.z;
    const int b  = bh >> 4;
    const int h  = bh & 15;
    const int m0 = blockIdx.y * 128;
    const int n0 = blockIdx.x * 128;

    const float* qbase = qb  + (size_t)(b * SEQ + m0) * D_MODEL + h * HEADDIM;
    const float* kbase = kb_ + (size_t)(b * SEQ + n0) * D_MODEL + h * HEADDIM;

    float acc[2][8][4] = {};

    for (int k0 = 0; k0 < HEADDIM; k0 += 32) {
        // Q tile 128x32 -> QF
        #pragma unroll
        for (int i = 0; i < 2; i++) {
            int idx = tid + i * 256;
            int rp = idx >> 3;
            int c4 = (idx & 7) * 4;
            int mt = rp >> 3;
            int r8 = rp & 7;
            const float* a0 = &qbase[(size_t)(mt * 16 + r8) * D_MODEL + k0 + c4];
            float4 vlo = *(const float4*)a0;
            float4 vhi = *(const float4*)(a0 + 8 * D_MODEL);
            int kbk = c4 >> 3;
            int off = ((c4 >> 2) & 1) * 2;
            uint32_t* base = (uint32_t*)&QF[mt][kbk][r8 * 4];
            *(uint2*)&base[0 * 4 + off] = make_uint2(f2tf32(vlo.x), f2tf32(vhi.x));
            *(uint2*)&base[1 * 4 + off] = make_uint2(f2tf32(vlo.y), f2tf32(vhi.y));
            *(uint2*)&base[2 * 4 + off] = make_uint2(f2tf32(vlo.z), f2tf32(vhi.z));
            *(uint2*)&base[3 * 4 + off] = make_uint2(f2tf32(vlo.w), f2tf32(vhi.w));
        }
        // K tile 128(n) x 32(k) -> KF (row of K == col-major B operand)
        #pragma unroll
        for (int i = 0; i < 2; i++) {
            int idx = tid + i * 256;
            int n  = idx >> 2;           // 0..127
            int c8 = (idx & 3) * 8;      // 0,8,16,24
            const float* p = &kbase[(size_t)n * D_MODEL + k0 + c8];
            float4 vlo = *(const float4*)p;
            float4 vhi = *(const float4*)(p + 4);
            int nt  = n >> 3;
            int gg  = n & 7;
            int kbk = c8 >> 3;
            KF[nt][kbk][gg * 4 + 0] = make_uint2(f2tf32(vlo.x), f2tf32(vhi.x));
            KF[nt][kbk][gg * 4 + 1] = make_uint2(f2tf32(vlo.y), f2tf32(vhi.y));
            KF[nt][kbk][gg * 4 + 2] = make_uint2(f2tf32(vlo.z), f2tf32(vhi.z));
            KF[nt][kbk][gg * 4 + 3] = make_uint2(f2tf32(vlo.w), f2tf32(vhi.w));
        }
        __syncthreads();

        #pragma unroll
        for (int kbk = 0; kbk < 4; kbk++) {
            uint4 a[2];
            a[0] = QF[wm * 2 + 0][kbk][lane];
            a[1] = QF[wm * 2 + 1][kbk][lane];
            uint2 bfr[8];
            #pragma unroll
            for (int jn = 0; jn < 8; jn++) bfr[jn] = KF[wn * 8 + jn][kbk][lane];
            #pragma unroll
            for (int im = 0; im < 2; im++)
                #pragma unroll
                for (int jn = 0; jn < 8; jn++)
                    mma_tf32(acc[im][jn], (const uint32_t*)&a[im], (const uint32_t*)&bfr[jn]);
        }
        __syncthreads();
    }

    const float scale = scale_ptr[0];
    float* obase = attn + ((size_t)bh * SEQ + m0) * SEQ + n0;
    #pragma unroll
    for (int im = 0; im < 2; im++) {
        int mb = wm * 32 + im * 16;
        #pragma unroll
        for (int jn = 0; jn < 8; jn++) {
            int n = wn * 64 + jn * 8 + 2 * kq;
            float* p0 = obase + (size_t)(mb + g) * SEQ + n;
            float* p1 = obase + (size_t)(mb + g + 8) * SEQ + n;
            p0[0] = acc[im][jn][0] * scale; p0[1] = acc[im][jn][1] * scale;
            p1[0] = acc[im][jn][2] * scale; p1[1] = acc[im][jn][3] * scale;
        }
    }
}

// ---------------------------------------------------------------------------
// Row softmax in place
// ---------------------------------------------------------------------------
__global__ void __launch_bounds__(256)
softmax_kernel(float* __restrict__ attn)
{
    const size_t row = blockIdx.x;
    float* p = attn + row * SEQ;
    const int tid = threadIdx.x;

    float local[8];
    float mx = -INFINITY;
    #pragma unroll
    for (int i = 0; i < 8; i++) {
        local[i] = p[tid + i * 256];
        mx = fmaxf(mx, local[i]);
    }

    __shared__ float red[256];
    red[tid] = mx;
    __syncthreads();
    #pragma unroll
    for (int s = 128; s > 0; s >>= 1) {
        if (tid < s) red[tid] = fmaxf(red[tid], red[tid + s]);
        __syncthreads();
    }
    mx = red[0];
    __syncthreads();

    float sum = 0.f;
    #pragma unroll
    for (int i = 0; i < 8; i++) {
        local[i] = __expf(local[i] - mx);
        sum += local[i];
    }
    red[tid] = sum;
    __syncthreads();
    #pragma unroll
    for (int s = 128; s > 0; s >>= 1) {
        if (tid < s) red[tid] += red[tid + s];
        __syncthreads();
    }
    const float inv = 1.0f / red[0];

    #pragma unroll
    for (int i = 0; i < 8; i++)
        p[tid + i * 256] = local[i] * inv;
}

// ---------------------------------------------------------------------------
// PV: ctx[m, h*64+d] = sum_j P[bh][m][j] * V[j, h*64+d]; tile 128x64, BK=32
// ---------------------------------------------------------------------------
__global__ void __launch_bounds__(256)
pv_tc(const float* __restrict__ attn, const float* __restrict__ vb,
      float* __restrict__ ctx)
{
    __shared__ uint4 PF[8][4][33];
    __shared__ uint2 VF[8][4][33];

    const int tid  = threadIdx.x;
    const int warp = tid >> 5;
    const int lane = tid & 31;
    const int g    = lane >> 2;
    const int kq   = lane & 3;
    const int wm   = warp >> 1;
    const int wn   = warp & 1;

    const int bh = blockIdx.z;
    const int b  = bh >> 4;
    const int h  = bh & 15;
    const int m0 = blockIdx.x * 128;

    const float* pbase = attn + ((size_t)bh * SEQ + m0) * SEQ;
    const float* vbase = vb + (size_t)b * SEQ * D_MODEL + h * HEADDIM;

    float acc[2][4][4] = {};

    for (int k0 = 0; k0 < SEQ; k0 += 32) {
        // P tile 128x32 -> PF
        #pragma unroll
        for (int i = 0; i < 2; i++) {
            int idx = tid + i * 256;
            int rp = idx >> 3;
            int c4 = (idx & 7) * 4;
            int mt = rp >> 3;
            int r8 = rp & 7;
            const float* a0 = &pbase[(size_t)(mt * 16 + r8) * SEQ + k0 + c4];
            float4 vlo = *(const float4*)a0;
            float4 vhi = *(const float4*)(a0 + 8 * SEQ);
            int kbk = c4 >> 3;
            int off = ((c4 >> 2) & 1) * 2;
            uint32_t* base = (uint32_t*)&PF[mt][kbk][r8 * 4];
            *(uint2*)&base[0 * 4 + off] = make_uint2(f2tf32(vlo.x), f2tf32(vhi.x));
            *(uint2*)&base[1 * 4 + off] = make_uint2(f2tf32(vlo.y), f2tf32(vhi.y));
            *(uint2*)&base[2 * 4 + off] = make_uint2(f2tf32(vlo.z), f2tf32(vhi.z));
            *(uint2*)&base[3 * 4 + off] = make_uint2(f2tf32(vlo.w), f2tf32(vhi.w));
        }
        // V tile 32(k) x 64(n) -> VF
        {
            int rp = tid >> 4;           // 0..15
            int c4 = (tid & 15) * 4;     // 0..60
            int kbk = rp >> 2;
            int rq  = rp & 3;
            const float* v0 = &vbase[(size_t)(k0 + kbk * 8 + rq) * D_MODEL + c4];
            float4 vlo = *(const float4*)v0;
            float4 vhi = *(const float4*)(v0 + 4 * D_MODEL);
            int nt = c4 >> 3;
            int gb = c4 & 7;
            VF[nt][kbk][(gb + 0) * 4 + rq] = make_uint2(f2tf32(vlo.x), f2tf32(vhi.x));
            VF[nt][kbk][(gb + 1) * 4 + rq] = make_uint2(f2tf32(vlo.y), f2tf32(vhi.y));
            VF[nt][kbk][(gb + 2) * 4 + rq] = make_uint2(f2tf32(vlo.z), f2tf32(vhi.z));
            VF[nt][kbk][(gb + 3) * 4 + rq] = make_uint2(f2tf32(vlo.w), f2tf32(vhi.w));
        }
        __syncthreads();

        #pragma unroll
        for (int kbk = 0; kbk < 4; kbk++) {
            uint4 a[2];
            a[0] = PF[wm * 2 + 0][kbk][lane];
            a[1] = PF[wm * 2 + 1][kbk][lane];
            uint2 bfr[4];
            #pragma unroll
            for (int jn = 0; jn < 4; jn++) bfr[jn] = VF[wn * 4 + jn][kbk][lane];
            #pragma unroll
            for (int im = 0; im < 2; im++)
                #pragma unroll
                for (int jn = 0; jn < 4; jn++)
                    mma_tf32(acc[im][jn], (const uint32_t*)&a[im], (const uint32_t*)&bfr[jn]);
        }
        __syncthreads();
    }

    #pragma unroll
    for (int im = 0; im < 2; im++) {
        int mb = b * SEQ + m0 + wm * 32 + im * 16;
        #pragma unroll
        for (int jn = 0; jn < 4; jn++) {
            int n = h * HEADDIM + wn * 32 + jn * 8 + 2 * kq;
            float* p0 = &ctx[(size_t)(mb + g) * D_MODEL + n];
            float* p1 = &ctx[(size_t)(mb + g + 8) * D_MODEL + n];
            p0[0] = acc[im][jn][0]; p0[1] = acc[im][jn][1];
            p1[0] = acc[im][jn][2]; p1[1] = acc[im][jn][3];
        }
    }
}

// ---------------------------------------------------------------------------
// Launch
// ---------------------------------------------------------------------------
extern "C" void kernel_launch(void* const* d_in, const int* in_sizes, int n_in,
                              void* d_out, int out_size)
{
    const float* Q     = (const float*)d_in[0];
    const float* Wq    = (const float*)d_in[1];
    const float* bq    = (const float*)d_in[2];
    const float* Wk    = (const float*)d_in[3];
    const float* bk    = (const float*)d_in[4];
    const float* Wv    = (const float*)d_in[5];
    const float* bv    = (const float*)d_in[6];
    const float* Wo    = (const float*)d_in[7];
    const float* bo    = (const float*)d_in[8];
    const float* scale = (const float*)d_in[9];

    const int M = in_sizes[0] / D_MODEL;   // B * SEQ
    const int B = M / SEQ;

    float* out = (float*)d_out;

    float *qp, *kp, *vp, *cp, *ap;
    cudaGetSymbolAddress((void**)&qp, g_q);
    cudaGetSymbolAddress((void**)&kp, g_k);
    cudaGetSymbolAddress((void**)&vp, g_v);
    cudaGetSymbolAddress((void**)&cp, g_ctx);
    cudaGetSymbolAddress((void**)&ap, g_attn);

    const size_t out_elems = (size_t)M * D_MODEL;
    float* attn = ((size_t)out_size > out_elems) ? (out + out_elems) : ap;

    dim3 gqkv(D_MODEL / 128, M / 128, 3);        // (8, 32, 3)
    qkv_proj_tc<<<gqkv, 256>>>(Q, Wq, bq, Wk, bk, Wv, bv, qp, kp, vp);

    dim3 gsc(SEQ / 128, SEQ / 128, B * NHEADS);  // (16, 16, 32)
    scores_tc<<<gsc, 256>>>(qp, kp, scale, attn);

    softmax_kernel<<<B * NHEADS * SEQ, 256>>>(attn);

    dim3 gpv(SEQ / 128, 1, B * NHEADS);          // (16, 1, 32)
    pv_tc<<<gpv, 256>>>(attn, vp, cp);

    dim3 gproj(D_MODEL / 128, M / 128);          // (8, 32)
    gemm_bias_tc<<<gproj, 256>>>(cp, Wo, bo, out);
}